// round 6
// baseline (speedup 1.0000x reference)
#include <cuda_runtime.h>
#include <cuda_bf16.h>

// PositionEncoding: out[b,s,:] = is_class ? E_class[class_id] : sincos(v * 2^i * pi)
// B=64, S=8192, 32 levels (E=64), CLASS_NUM=4096.
//
// R5: kernel is LTS-bound (~207MB L2 traffic at the ~6300 B/cyc measured cap);
// compute changes proved irrelevant (R2==R4 at 23.0us). Remaining gap to the
// cap is latency exposure (issue 31% @ occ 85%). Fix: UNROLL 8 tokens/thread
// -> 8 gathers + 6 vector loads in flight per thread, same sacred store shape
// (16 threads/token, one contiguous float4 each = perfect 512B warp stores).
//
// Angle math (FP64-free "turns", see earlier rounds): angle for level i is
// exactly 2^i * a0, a0 = fl32(v*pi_f). u = frac(a0*(1/2pi)*2^i) via two-float
// 1/2pi (~47 bits; pow2 scale & frac exact in fp32). One __sincosf for the
// even level; odd level via double-angle FMAs. Angle err ~5e-5 << 1e-3 tol.

#define NTOK   (64 * 8192)     // 524288 tokens
#define UNROLL 8               // tokens per thread

__global__ __launch_bounds__(256)
void pos_enc_kernel(const float4* __restrict__ values4,    // [NTOK/4]
                    const float4* __restrict__ E_class,    // [4096][16] float4
                    const int4*  __restrict__ class_ids4,  // [NTOK/4]
                    const int4*  __restrict__ is_class4,   // [NTOK/4]
                    float4* __restrict__ out)               // [NTOK][16] float4
{
    unsigned gid  = blockIdx.x * blockDim.x + threadIdx.x;
    unsigned t    = gid & 15u;          // float4 slot -> levels 2t, 2t+1
    unsigned grp  = gid >> 4;           // token group (8 tokens)
    unsigned tok0 = grp * UNROLL;
    if (tok0 >= NTOK) return;

    // two-float 1/(2pi): C_HI + C_LO ~ 47 bits (folded at compile time)
    constexpr double INV2PI_D = 0.15915494309189533577;
    constexpr float  C_HI = (float)INV2PI_D;
    constexpr float  C_LO = (float)(INV2PI_D - (double)C_HI);
    const float PI_F     = 3.14159265358979323846f;   // rounds to pi_f32
    const float TWO_PI_F = 6.28318530717958647693f;

    // 2^(2t) as exact fp32 via exponent bits
    float scale_e = __uint_as_float((127u + 2u * t) << 23);

    // ---- 6 vector loads cover all 24 per-token scalars (front-loaded MLP) ----
    float4 va = __ldg(&values4[2u * grp]);
    float4 vb = __ldg(&values4[2u * grp + 1u]);
    int4   ca = __ldg(&class_ids4[2u * grp]);
    int4   cb = __ldg(&class_ids4[2u * grp + 1u]);
    int4   ma = __ldg(&is_class4[2u * grp]);
    int4   mb = __ldg(&is_class4[2u * grp + 1u]);

    float v[UNROLL]   = { va.x, va.y, va.z, va.w, vb.x, vb.y, vb.z, vb.w };
    int   cid[UNROLL] = { ca.x, ca.y, ca.z, ca.w, cb.x, cb.y, cb.z, cb.w };
    int   ic[UNROLL]  = { ma.x, ma.y, ma.z, ma.w, mb.x, mb.y, mb.z, mb.w };

    // ---- issue all predicated E_class gathers early (8 outstanding) ----
    float4 cls[UNROLL];
#pragma unroll
    for (int j = 0; j < UNROLL; j++) {
        if (ic[j] == 1)
            cls[j] = __ldg(&E_class[(unsigned)cid[j] * 16u + t]);
    }

    // ---- compute + streaming store ----
#pragma unroll
    for (int j = 0; j < UNROLL; j++) {
        float4 o;
        if (ic[j] == 1) {
            o = cls[j];
        } else {
            float a0   = v[j] * PI_F;                 // fl32(v*pi) — matches reference
            float s_hi = a0 * C_HI;
            float perr = fmaf(a0, C_HI, -s_hi);       // exact residual of a0*C_HI
            float s_lo = fmaf(a0, C_LO, perr);        // two-float tail, ~47 bits total
            float y_hi = s_hi * scale_e;              // exact (pow2 scale)
            float y_lo = s_lo * scale_e;              // exact
            float f    = (y_hi - floorf(y_hi)) + (y_lo - floorf(y_lo)); // exact fracs
            float w0   = f - rintf(f);                // turn in [-0.5, 0.5]

            float s0, c0;
            __sincosf(w0 * TWO_PI_F, &s0, &c0);       // level 2t
            float s1 = 2.0f * s0 * c0;                // level 2t+1 via double angle
            float c1 = fmaf(-2.0f * s0, s0, 1.0f);
            o = make_float4(s0, c0, s1, c1);
        }
        __stcs(&out[(tok0 + j) * 16u + t], o);        // evict-first: never re-read
    }
}

extern "C" void kernel_launch(void* const* d_in, const int* in_sizes, int n_in,
                              void* d_out, int out_size)
{
    const float4* values4    = (const float4*)d_in[0];
    const float4* E_class    = (const float4*)d_in[1];
    const int4*   class_ids4 = (const int4*)d_in[2];
    const int4*   is_class4  = (const int4*)d_in[3];
    float4*       out        = (float4*)d_out;

    const int threads = 256;
    const long long total = (long long)(NTOK / UNROLL) * 16;   // 1,048,576 threads
    const int blocks  = (int)((total + threads - 1) / threads);
    pos_enc_kernel<<<blocks, threads>>>(values4, E_class, class_ids4, is_class4, out);
}